// round 14
// baseline (speedup 1.0000x reference)
#include <cuda_runtime.h>
#include <stdint.h>
#include <math.h>

#define BB 32768
#define DD 64
#define HH 256
#define DTF 0.125f

// ---------------- device scratch (static, no runtime allocation) ----------------
__device__ float g_y[BB*DD];
__device__ float g_logp[BB];
__device__ float g_kz[6][BB*DD];
__device__ float g_kd[6][BB];
__device__ float g_c[BB*HH];
__device__ float g_csum[BB];
__device__ unsigned long long g_w2kp[128*64];   // {W2[2k][d], W2[2k+1][d]} packed pairs

// ---------------- packed f32x2 helpers (FFMA2: only reachable via explicit PTX) ----------------
#define FFMA2(acc, a, b) \
    asm("fma.rn.f32x2 %0, %1, %2, %3;" : "=l"(acc) : "l"(a), "l"(b), "l"(acc))
#define PACK2(dst, lo, hi) \
    asm("mov.b64 %0, {%1, %2};" : "=l"(dst) : "r"(lo), "r"(hi))
#define UNPACK2(lo, hi, src) \
    asm("mov.b64 {%0, %1}, %2;" : "=r"(lo), "=r"(hi) : "l"(src))

// 32-byte evict_last global load (v8.b32 is the only f32-class form ptxas accepts)
__device__ __forceinline__ void ldg_evl8(const float* p, float4& lo, float4& hi){
    asm("ld.global.nc.L2::evict_last.v8.b32 {%0,%1,%2,%3,%4,%5,%6,%7}, [%8];"
        : "=f"(lo.x), "=f"(lo.y), "=f"(lo.z), "=f"(lo.w),
          "=f"(hi.x), "=f"(hi.y), "=f"(hi.z), "=f"(hi.w)
        : "l"(p));
}

// accurate fast tanh: 2 MUFU (ex2, rcp); ~1e-6 rel err
__device__ __forceinline__ float tanh_fast(float x){
    float a = fabsf(x);
    float m = a * -2.8853900817779268f;   // -2*log2(e)
    float e; asm("ex2.approx.f32 %0, %1;" : "=f"(e) : "f"(m));
    float den = 1.f + e;
    float r; asm("rcp.approx.f32 %0, %1;" : "=f"(r) : "f"(den));
    return copysignf((1.f - e) * r, x);
}

// ---------------- init: copy y, zero logp ----------------
__global__ void init_kernel(const float* __restrict__ y){
    int i = blockIdx.x*256 + threadIdx.x;
    g_y[i] = y[i];
    if (i < BB) g_logp[i] = 0.f;
}

// ---------------- prep: pack W2 k-pairs ----------------
__global__ void prep_kernel(const float* __restrict__ W2){
    int i = blockIdx.x*256 + threadIdx.x;   // 8192
    int k2 = i >> 6, d = i & 63;
    uint32_t lo = __float_as_uint(W2[(size_t)(2*k2)*DD + d]);
    uint32_t hi = __float_as_uint(W2[(size_t)(2*k2+1)*DD + d]);
    unsigned long long p; PACK2(p, lo, hi);
    g_w2kp[i] = p;
}

// ---------------- precompute: c = (e@W2^T) * (e@W1z), csum = row-sum(c) ----------------
__global__ __launch_bounds__(512,1) void precompute_kernel(
    const float* __restrict__ e, const float* __restrict__ W1, const float* __restrict__ W2){
    extern __shared__ float sm[];
    float* W1s = sm;            // [64][256]
    float* W2T = sm + 16384;    // [64][256]  (transposed W2)
    float* es  = sm + 32768;    // [64][64]
    int tid = threadIdx.x;
    int row0 = blockIdx.x*64;

    for (int i=tid; i<4096; i+=512) ((float4*)W1s)[i] = ((const float4*)W1)[i];
    for (int i=tid; i<HH*DD; i+=512){ int h = i>>6, d = i&63; W2T[d*HH + h] = W2[i]; }
    for (int i=tid; i<1024; i+=512) ((float4*)es)[i] = ((const float4*)(e + (size_t)row0*DD))[i];
    __syncthreads();

    int ry = tid>>5, hx = tid&31;   // rows ry*4..+3, h cols hx*8..+7
    float s1[4][8], s2[4][8];
    #pragma unroll
    for (int i=0;i<4;i++)
        #pragma unroll
        for (int j=0;j<8;j++){ s1[i][j]=0.f; s2[i][j]=0.f; }

    for (int d=0; d<DD; d++){
        float ev[4];
        #pragma unroll
        for (int i=0;i<4;i++) ev[i] = es[(ry*4+i)*DD + d];
        const float* p1 = &W1s[d*HH + hx*8];
        const float* p2 = &W2T[d*HH + hx*8];
        float4 a1 = *(const float4*)p1,  b1v = *(const float4*)(p1+4);
        float4 a2 = *(const float4*)p2,  b2v = *(const float4*)(p2+4);
        float w1v[8] = {a1.x,a1.y,a1.z,a1.w,b1v.x,b1v.y,b1v.z,b1v.w};
        float w2v[8] = {a2.x,a2.y,a2.z,a2.w,b2v.x,b2v.y,b2v.z,b2v.w};
        #pragma unroll
        for (int i=0;i<4;i++)
            #pragma unroll
            for (int j=0;j<8;j++){
                s2[i][j] = fmaf(ev[i], w1v[j], s2[i][j]);
                s1[i][j] = fmaf(ev[i], w2v[j], s1[i][j]);
            }
    }
    #pragma unroll
    for (int i=0;i<4;i++){
        float cv[8]; float p = 0.f;
        #pragma unroll
        for (int j=0;j<8;j++){ cv[j] = s1[i][j]*s2[i][j]; p += cv[j]; }
        int r = row0 + ry*4 + i;
        float4* dst = (float4*)&g_c[(size_t)r*HH + hx*8];
        dst[0] = make_float4(cv[0],cv[1],cv[2],cv[3]);
        dst[1] = make_float4(cv[4],cv[5],cv[6],cv[7]);
        #pragma unroll
        for (int o=16;o;o>>=1) p += __shfl_xor_sync(0xffffffffu, p, o);
        if (hx==0) g_csum[r] = p;
    }
}

// ---------------- fused RHS: 512 threads, 64-row tiles, 2 CTAs/SM ----------------
// SMEM float-index map (time-shared buffers):
//   wbuf : 0     .. 16384   (64KB)  phase A: W1 f32 [64][256]; phase B: W2 k-pair image u64[128][64]
//   zh   : 16384 .. 20736            phase A: zs f32 [64][64]; phase B: hs u64 [64][34] (padded)
//   tb   : 20736 .. 20992
//   b2s  : 20992 .. 21056
#define WB_OFF 0
#define ZH_OFF 16384
#define TB_OFF 20736
#define B2_OFF 20992
#define SMEM_RHS_BYTES (21056*4)

__global__ __launch_bounds__(512,2) void rhs_kernel(
    float t, int stage, float c0,float c1,float c2,float c3,float c4,
    const float* __restrict__ W1, const float* __restrict__ b1,
    const float* __restrict__ b2){
    extern __shared__ float sm[];
    float* wbuf = sm + WB_OFF;
    float* zs   = sm + ZH_OFF;
    unsigned long long* hsu = (unsigned long long*)(sm + ZH_OFF);
    float* tb   = sm + TB_OFF;
    float* b2s  = sm + B2_OFF;
    int tid = threadIdx.x;
    int row0 = blockIdx.x*64;

    // phase A fill: W1 -> wbuf, tb, b2s
    for (int i=tid; i<4096; i+=512)
        ((float4*)wbuf)[i] = __ldg(((const float4*)W1) + i);
    if (tid < HH)                 tb[tid]     = fmaf(t, __ldg(&W1[DD*HH + tid]), __ldg(&b1[tid]));
    if (tid >= HH && tid < HH+DD) b2s[tid-HH] = __ldg(&b2[tid-HH]);

    // build zs = y + sum cf_j k_j
    const float cf[5] = {c0,c1,c2,c3,c4};
    {
        const float4* ybase = (const float4*)(g_y + (size_t)row0*DD);
        for (int i=tid; i<1024; i+=512){
            float4 v = ybase[i];
            for (int j=0;j<stage;j++){
                float4 k = ((const float4*)(g_kz[j] + (size_t)row0*DD))[i];
                v.x = fmaf(cf[j],k.x,v.x); v.y = fmaf(cf[j],k.y,v.y);
                v.z = fmaf(cf[j],k.z,v.z); v.w = fmaf(cf[j],k.w,v.w);
            }
            ((float4*)zs)[i] = v;
        }
    }
    __syncthreads();

    // ---- GEMM1 (packed): a[64x256] = zs[64x64] @ W1[64x256] ----
    // thread (ry,hx): rows ry*4..+3 ; h cols hx*8..+7 (4 packed pairs)
    int ry = tid>>5, hx = tid&31;
    unsigned long long acc2[4][4];
    #pragma unroll
    for (int i=0;i<4;i++)
        #pragma unroll
        for (int j=0;j<4;j++) acc2[i][j] = 0ull;

    for (int d0=0; d0<DD; d0+=4){
        float zq[4][4];
        #pragma unroll
        for (int i=0;i<4;i++){
            float4 z4 = *(const float4*)&zs[(ry*4+i)*DD + d0];
            zq[i][0]=z4.x; zq[i][1]=z4.y; zq[i][2]=z4.z; zq[i][3]=z4.w;
        }
        #pragma unroll
        for (int dd=0; dd<4; dd++){
            const ulonglong2* wp = (const ulonglong2*)&wbuf[(d0+dd)*HH + hx*8];
            ulonglong2 wa = wp[0], wb = wp[1];
            unsigned long long wv[4] = {wa.x, wa.y, wb.x, wb.y};
            #pragma unroll
            for (int i=0;i<4;i++){
                unsigned long long z2;
                uint32_t zb = __float_as_uint(zq[i][dd]);
                PACK2(z2, zb, zb);
                #pragma unroll
                for (int j=0;j<4;j++) FFMA2(acc2[i][j], z2, wv[j]);
            }
        }
    }
    __syncthreads();   // all W1/zs reads complete -> buffers reusable

    // phase B fill: W2 k-pair image -> wbuf (64KB = 4096 ulonglong2; visible at first chunk barrier)
    for (int i=tid; i<4096; i+=512)
        ((ulonglong2*)wbuf)[i] = __ldg(((const ulonglong2*)g_w2kp) + i);

    // ---- bias + tanh + divergence dot (skipped at stage 1: B_TAB[1]==0) ----
    const bool do_div = (stage != 1);
    {
        float4 tbA = *(const float4*)&tb[hx*8];
        float4 tbB = *(const float4*)&tb[hx*8 + 4];
        float tba[8] = {tbA.x,tbA.y,tbA.z,tbA.w,tbB.x,tbB.y,tbB.z,tbB.w};
        size_t crow = ((size_t)row0 + ry*4)*HH + hx*8;
        float4 cA, cB;
        if (do_div) ldg_evl8(g_c + crow, cA, cB);
        #pragma unroll
        for (int i=0;i<4;i++){
            float4 c0v = cA, c1v = cB;
            if (do_div && i<3) ldg_evl8(g_c + crow + (size_t)(i+1)*HH, cA, cB);
            float hv[8];
            #pragma unroll
            for (int j=0;j<4;j++){
                uint32_t u0, u1;
                UNPACK2(u0, u1, acc2[i][j]);
                hv[2*j]   = tanh_fast(__uint_as_float(u0) + tba[2*j]);
                hv[2*j+1] = tanh_fast(__uint_as_float(u1) + tba[2*j+1]);
                PACK2(acc2[i][j], __float_as_uint(hv[2*j]), __float_as_uint(hv[2*j+1]));
            }
            if (do_div){
                float p;
                p  = c0v.x*hv[0]*hv[0];
                p  = fmaf(c0v.y*hv[1], hv[1], p);
                p  = fmaf(c0v.z*hv[2], hv[2], p);
                p  = fmaf(c0v.w*hv[3], hv[3], p);
                p  = fmaf(c1v.x*hv[4], hv[4], p);
                p  = fmaf(c1v.y*hv[5], hv[5], p);
                p  = fmaf(c1v.z*hv[6], hv[6], p);
                p  = fmaf(c1v.w*hv[7], hv[7], p);
                #pragma unroll
                for (int o=16;o;o>>=1) p += __shfl_xor_sync(0xffffffffu, p, o);
                if (hx==0){
                    int r = row0 + ry*4 + i;
                    g_kd[stage][r] = p - __ldg(&g_csum[r]);
                }
            }
        }
    }

    // ---- GEMM2 (k-packed, from smem): dz[64x64] = h[64x256] @ W2[256x64] ----
    // h pairs already packed in acc2; W2 pairs in wbuf. Lanes hold {even-k, odd-k} sums.
    int rg = tid>>4, dg = tid&15;       // rows rg*2..+1 ; d cols dg*4..+3
    unsigned long long dzk[2][4];
    #pragma unroll
    for (int i=0;i<2;i++)
        #pragma unroll
        for (int c=0;c<4;c++) dzk[i][c] = 0ull;

    const unsigned long long* wb64 = (const unsigned long long*)wbuf;
    for (int ci=0; ci<4; ci++){
        __syncthreads();    // W2 copy visible (ci=0); prior chunk reads done (ci>0)
        if ((hx>>3) == ci){
            int hb = (hx&7)*4;
            #pragma unroll
            for (int i=0;i<4;i++)
                #pragma unroll
                for (int j=0;j<4;j++)
                    hsu[(ry*4+i)*34 + hb + j] = acc2[i][j];
        }
        __syncthreads();
        #pragma unroll 4
        for (int k2=0; k2<32; k2++){
            const ulonglong2* wp = (const ulonglong2*)(wb64 + (size_t)(ci*32 + k2)*DD + dg*4);
            ulonglong2 wA = wp[0], wB = wp[1];
            #pragma unroll
            for (int i=0;i<2;i++){
                unsigned long long hp = hsu[(rg*2+i)*34 + k2];
                FFMA2(dzk[i][0], hp, wA.x);
                FFMA2(dzk[i][1], hp, wA.y);
                FFMA2(dzk[i][2], hp, wB.x);
                FFMA2(dzk[i][3], hp, wB.y);
            }
        }
    }

    float4 bb = *(const float4*)&b2s[dg*4];
    #pragma unroll
    for (int i=0;i<2;i++){
        float r[4];
        #pragma unroll
        for (int c=0;c<4;c++){
            uint32_t lo, hi;
            UNPACK2(lo, hi, dzk[i][c]);
            r[c] = __uint_as_float(lo) + __uint_as_float(hi);
        }
        float4 o = make_float4(r[0]+bb.x, r[1]+bb.y, r[2]+bb.z, r[3]+bb.w);
        *(float4*)&g_kz[stage][(size_t)(row0+rg*2+i)*DD + dg*4] = o;
    }
}

// ---------------- combine: y += dt*sum b_j k_j ; logp += dt*sum b_j kd_j ----------------
__global__ void combine_kernel(float dt){
    int i = blockIdx.x*256 + threadIdx.x;   // over BB*DD/4 float4
    const float b0 = (float)(35.0/384.0);
    const float b2 = (float)(500.0/1113.0);
    const float b3 = (float)(125.0/192.0);
    const float b4 = (float)(-2187.0/6784.0);
    const float b5 = (float)(11.0/84.0);
    float4 y = ((float4*)g_y)[i];
    float4 k0 = ((const float4*)g_kz[0])[i];
    float4 k2 = ((const float4*)g_kz[2])[i];
    float4 k3 = ((const float4*)g_kz[3])[i];
    float4 k4 = ((const float4*)g_kz[4])[i];
    float4 k5 = ((const float4*)g_kz[5])[i];
    float sx = b0*k0.x + b2*k2.x + b3*k3.x + b4*k4.x + b5*k5.x;
    float sy = b0*k0.y + b2*k2.y + b3*k3.y + b4*k4.y + b5*k5.y;
    float sz = b0*k0.z + b2*k2.z + b3*k3.z + b4*k4.z + b5*k5.z;
    float sw = b0*k0.w + b2*k2.w + b3*k3.w + b4*k4.w + b5*k5.w;
    y.x = fmaf(dt, sx, y.x); y.y = fmaf(dt, sy, y.y);
    y.z = fmaf(dt, sz, y.z); y.w = fmaf(dt, sw, y.w);
    ((float4*)g_y)[i] = y;
    if (i < BB){
        float s = b0*g_kd[0][i] + b2*g_kd[2][i] + b3*g_kd[3][i] + b4*g_kd[4][i] + b5*g_kd[5][i];
        g_logp[i] = fmaf(dt, s, g_logp[i]);
    }
}

// ---------------- epilogue: out = [z flat | log_px] ----------------
__global__ void final_kernel(float* __restrict__ out, int out_size){
    int gw = blockIdx.x*256 + threadIdx.x;
    int r = gw >> 5, lane = gw & 31;       // one warp per row
    float z0 = g_y[r*DD + lane];
    float z1 = g_y[r*DD + 32 + lane];
    out[r*DD + lane]      = z0;
    out[r*DD + 32 + lane] = z1;
    float s = fmaf(z0, z0, z1*z1);
    #pragma unroll
    for (int o=16;o;o>>=1) s += __shfl_xor_sync(0xffffffffu, s, o);
    if (lane==0){
        int oidx = BB*DD + r;
        if (oidx < out_size)
            out[oidx] = fmaf(-0.5f, s, -((float)DD)*0.91893853320467274178f) - g_logp[r];
    }
}

// ---------------- host ----------------
static const double A1t[1]={0.2};
static const double A2t[2]={3.0/40.0, 9.0/40.0};
static const double A3t[3]={44.0/45.0, -56.0/15.0, 32.0/9.0};
static const double A4t[4]={19372.0/6561.0, -25360.0/2187.0, 64448.0/6561.0, -212.0/729.0};
static const double A5t[5]={9017.0/3168.0, -355.0/33.0, 46732.0/5247.0, 49.0/176.0, -5103.0/18656.0};
static const double* ATAB[6]={0, A1t, A2t, A3t, A4t, A5t};
static const double CTAB[6]={0.0, 0.2, 0.3, 0.8, 8.0/9.0, 1.0};

extern "C" void kernel_launch(void* const* d_in, const int* in_sizes, int n_in,
                              void* d_out, int out_size){
    const float* y  = (const float*)d_in[0];
    const float* e  = (const float*)d_in[1];
    const float* W1 = (const float*)d_in[2];
    const float* b1 = (const float*)d_in[3];
    const float* W2 = (const float*)d_in[4];
    const float* b2 = (const float*)d_in[5];

    cudaFuncSetAttribute(rhs_kernel,        cudaFuncAttributeMaxDynamicSharedMemorySize, SMEM_RHS_BYTES);
    cudaFuncSetAttribute(precompute_kernel, cudaFuncAttributeMaxDynamicSharedMemorySize, 147456);

    init_kernel<<<8192,256>>>(y);
    prep_kernel<<<32,256>>>(W2);
    precompute_kernel<<<512,512,147456>>>(e, W1, W2);

    double dt = 1.0/8.0;
    for (int s=0; s<8; s++){
        double t0 = s*dt;
        for (int i=0; i<6; i++){
            float cf[5] = {0.f,0.f,0.f,0.f,0.f};
            for (int j=0; j<i; j++) cf[j] = (float)(dt*ATAB[i][j]);
            rhs_kernel<<<512,512,SMEM_RHS_BYTES>>>(
                (float)(t0 + CTAB[i]*dt), i, cf[0],cf[1],cf[2],cf[3],cf[4],
                W1, b1, b2);
        }
        combine_kernel<<<2048,256>>>((float)dt);
    }
    final_kernel<<<4096,256>>>((float*)d_out, out_size);
}

// round 15
// speedup vs baseline: 1.5616x; 1.5616x over previous
#include <cuda_runtime.h>
#include <stdint.h>
#include <math.h>

#define BB 32768
#define DD 64
#define HH 256
#define DTF 0.125f

// ---------------- device scratch (static, no runtime allocation) ----------------
__device__ float g_y[BB*DD];
__device__ float g_logp[BB];
__device__ float g_kz[6][BB*DD];
__device__ float g_kd[6][BB];
__device__ float g_c[BB*HH];
__device__ float g_csum[BB];

// ---------------- packed f32x2 helpers (FFMA2: only reachable via explicit PTX) ----------------
#define FFMA2(acc, a, b) \
    asm("fma.rn.f32x2 %0, %1, %2, %3;" : "=l"(acc) : "l"(a), "l"(b), "l"(acc))
#define PACK2(dst, lo, hi) \
    asm("mov.b64 %0, {%1, %2};" : "=l"(dst) : "r"(lo), "r"(hi))
#define UNPACK2(lo, hi, src) \
    asm("mov.b64 {%0, %1}, %2;" : "=r"(lo), "=r"(hi) : "l"(src))

// 32-byte evict_last global load (v8.b32 is the only f32-class form ptxas accepts)
__device__ __forceinline__ void ldg_evl8(const float* p, float4& lo, float4& hi){
    asm("ld.global.nc.L2::evict_last.v8.b32 {%0,%1,%2,%3,%4,%5,%6,%7}, [%8];"
        : "=f"(lo.x), "=f"(lo.y), "=f"(lo.z), "=f"(lo.w),
          "=f"(hi.x), "=f"(hi.y), "=f"(hi.z), "=f"(hi.w)
        : "l"(p));
}

// accurate fast tanh: 2 MUFU (ex2, rcp); ~1e-6 rel err
__device__ __forceinline__ float tanh_fast(float x){
    float a = fabsf(x);
    float m = a * -2.8853900817779268f;   // -2*log2(e)
    float e; asm("ex2.approx.f32 %0, %1;" : "=f"(e) : "f"(m));
    float den = 1.f + e;
    float r; asm("rcp.approx.f32 %0, %1;" : "=f"(r) : "f"(den));
    return copysignf((1.f - e) * r, x);
}

// ---------------- init: copy y, zero logp ----------------
__global__ void init_kernel(const float* __restrict__ y){
    int i = blockIdx.x*256 + threadIdx.x;      // grid covers BB*DD exactly
    g_y[i] = y[i];
    if (i < BB) g_logp[i] = 0.f;
}

// ---------------- precompute: c = (e@W2^T) * (e@W1z), csum = row-sum(c) ----------------
__global__ __launch_bounds__(512,1) void precompute_kernel(
    const float* __restrict__ e, const float* __restrict__ W1, const float* __restrict__ W2){
    extern __shared__ float sm[];
    float* W1s = sm;            // [64][256]
    float* W2T = sm + 16384;    // [64][256]  (transposed W2)
    float* es  = sm + 32768;    // [64][64]
    int tid = threadIdx.x;
    int row0 = blockIdx.x*64;

    for (int i=tid; i<4096; i+=512) ((float4*)W1s)[i] = ((const float4*)W1)[i];
    for (int i=tid; i<HH*DD; i+=512){ int h = i>>6, d = i&63; W2T[d*HH + h] = W2[i]; }
    for (int i=tid; i<1024; i+=512) ((float4*)es)[i] = ((const float4*)(e + (size_t)row0*DD))[i];
    __syncthreads();

    int ry = tid>>5, hx = tid&31;   // rows ry*4..+3, h cols hx*8..+7
    float s1[4][8], s2[4][8];
    #pragma unroll
    for (int i=0;i<4;i++)
        #pragma unroll
        for (int j=0;j<8;j++){ s1[i][j]=0.f; s2[i][j]=0.f; }

    for (int d=0; d<DD; d++){
        float ev[4];
        #pragma unroll
        for (int i=0;i<4;i++) ev[i] = es[(ry*4+i)*DD + d];
        const float* p1 = &W1s[d*HH + hx*8];
        const float* p2 = &W2T[d*HH + hx*8];
        float4 a1 = *(const float4*)p1,  b1v = *(const float4*)(p1+4);
        float4 a2 = *(const float4*)p2,  b2v = *(const float4*)(p2+4);
        float w1v[8] = {a1.x,a1.y,a1.z,a1.w,b1v.x,b1v.y,b1v.z,b1v.w};
        float w2v[8] = {a2.x,a2.y,a2.z,a2.w,b2v.x,b2v.y,b2v.z,b2v.w};
        #pragma unroll
        for (int i=0;i<4;i++)
            #pragma unroll
            for (int j=0;j<8;j++){
                s2[i][j] = fmaf(ev[i], w1v[j], s2[i][j]);
                s1[i][j] = fmaf(ev[i], w2v[j], s1[i][j]);
            }
    }
    #pragma unroll
    for (int i=0;i<4;i++){
        float cv[8]; float p = 0.f;
        #pragma unroll
        for (int j=0;j<8;j++){ cv[j] = s1[i][j]*s2[i][j]; p += cv[j]; }
        int r = row0 + ry*4 + i;
        float4* dst = (float4*)&g_c[(size_t)r*HH + hx*8];
        dst[0] = make_float4(cv[0],cv[1],cv[2],cv[3]);
        dst[1] = make_float4(cv[4],cv[5],cv[6],cv[7]);
        #pragma unroll
        for (int o=16;o;o>>=1) p += __shfl_xor_sync(0xffffffffu, p, o);
        if (hx==0) g_csum[r] = p;
    }
}

// ---------------- fused RHS (packed f32x2; duplicated-h GEMM2) ----------------
// SMEM float-index map:
//   W1s [64][256]          : 0     .. 16384
//   W2s [256][64]          : 16384 .. 32768
//   union {                : 32768 .. 49664
//     zs  f32 [128][64]      (phase A; 8192 floats at 32768..40960)
//     hs2 u64 [128][66]      (phase B; dup {h,h} per col, chunk-local 64 cols)
//   }
//   tb  [256]              : 49664 .. 49920
//   b2s [64]               : 49920 .. 49984
#define SMEM_RHS_BYTES (49984*4)

__global__ __launch_bounds__(512,1) void rhs_kernel(
    float t, int stage, float c0,float c1,float c2,float c3,float c4,
    const float* __restrict__ W1, const float* __restrict__ b1,
    const float* __restrict__ W2, const float* __restrict__ b2){
    extern __shared__ float sm[];
    float* W1s  = sm;
    float* W2s  = sm + 16384;
    float* zs   = sm + 32768;
    unsigned long long* hsu = (unsigned long long*)(sm + 32768);
    float* tb   = sm + 49664;
    float* b2s  = sm + 49920;
    int tid = threadIdx.x;
    int row0 = blockIdx.x*128;

    for (int i=tid; i<4096; i+=512) ((float4*)W1s)[i] = ((const float4*)W1)[i];
    for (int i=tid; i<4096; i+=512) ((float4*)W2s)[i] = ((const float4*)W2)[i];
    if (tid < HH)                 tb[tid]       = fmaf(t, __ldg(&W1[DD*HH + tid]), __ldg(&b1[tid]));
    if (tid >= HH && tid < HH+DD) b2s[tid-HH]   = __ldg(&b2[tid-HH]);

    const float cf[5] = {c0,c1,c2,c3,c4};
    {
        const float4* ybase = (const float4*)(g_y + (size_t)row0*DD);
        for (int i=tid; i<2048; i+=512){
            float4 v = ybase[i];
            for (int j=0;j<stage;j++){
                float4 k = ((const float4*)(g_kz[j] + (size_t)row0*DD))[i];
                v.x = fmaf(cf[j],k.x,v.x); v.y = fmaf(cf[j],k.y,v.y);
                v.z = fmaf(cf[j],k.z,v.z); v.w = fmaf(cf[j],k.w,v.w);
            }
            ((float4*)zs)[i] = v;
        }
    }
    __syncthreads();

    // ---- GEMM1 (packed): a[128x256] = zs[128x64] @ W1s[64x256]
    // thread (ry,hx): rows ry*8..+7 ; h cols hx*8..+7 (4 packed pairs)
    int ry = tid>>5, hx = tid&31;
    unsigned long long acc2[8][4];
    #pragma unroll
    for (int i=0;i<8;i++)
        #pragma unroll
        for (int j=0;j<4;j++) acc2[i][j] = 0ull;

    for (int d0=0; d0<DD; d0+=4){
        float zq[8][4];
        #pragma unroll
        for (int i=0;i<8;i++){
            float4 z4 = *(const float4*)&zs[(ry*8+i)*DD + d0];
            zq[i][0]=z4.x; zq[i][1]=z4.y; zq[i][2]=z4.z; zq[i][3]=z4.w;
        }
        #pragma unroll
        for (int dd=0; dd<4; dd++){
            const ulonglong2* wp = (const ulonglong2*)&W1s[(d0+dd)*HH + hx*8];
            ulonglong2 wa = wp[0], wb = wp[1];
            unsigned long long wv[4] = {wa.x, wa.y, wb.x, wb.y};
            #pragma unroll
            for (int i=0;i<8;i++){
                unsigned long long z2;
                uint32_t zb = __float_as_uint(zq[i][dd]);
                PACK2(z2, zb, zb);
                #pragma unroll
                for (int j=0;j<4;j++) FFMA2(acc2[i][j], z2, wv[j]);
            }
        }
    }

    // ---- bias + tanh + divergence dot (skipped at stage 1: B_TAB[1]==0) ----
    size_t grow0 = (size_t)row0;
    const bool do_div = (stage != 1);
    {
        float4 tbA = *(const float4*)&tb[hx*8];
        float4 tbB = *(const float4*)&tb[hx*8 + 4];
        float tba[8] = {tbA.x,tbA.y,tbA.z,tbA.w,tbB.x,tbB.y,tbB.z,tbB.w};
        size_t crow = (grow0 + ry*8)*HH + hx*8;
        float4 cA, cB;
        if (do_div) ldg_evl8(g_c + crow, cA, cB);
        #pragma unroll
        for (int i=0;i<8;i++){
            float4 c0v = cA, c1v = cB;
            if (do_div && i<7) ldg_evl8(g_c + crow + (size_t)(i+1)*HH, cA, cB);
            float hv[8];
            #pragma unroll
            for (int j=0;j<4;j++){
                uint32_t u0, u1;
                UNPACK2(u0, u1, acc2[i][j]);
                hv[2*j]   = tanh_fast(__uint_as_float(u0) + tba[2*j]);
                hv[2*j+1] = tanh_fast(__uint_as_float(u1) + tba[2*j+1]);
                PACK2(acc2[i][j], __float_as_uint(hv[2*j]), __float_as_uint(hv[2*j+1]));
            }
            if (do_div){
                float p;
                p  = c0v.x*hv[0]*hv[0];
                p  = fmaf(c0v.y*hv[1], hv[1], p);
                p  = fmaf(c0v.z*hv[2], hv[2], p);
                p  = fmaf(c0v.w*hv[3], hv[3], p);
                p  = fmaf(c1v.x*hv[4], hv[4], p);
                p  = fmaf(c1v.y*hv[5], hv[5], p);
                p  = fmaf(c1v.z*hv[6], hv[6], p);
                p  = fmaf(c1v.w*hv[7], hv[7], p);
                #pragma unroll
                for (int o=16;o;o>>=1) p += __shfl_xor_sync(0xffffffffu, p, o);
                if (hx==0){
                    int r = row0 + ry*8 + i;
                    g_kd[stage][r] = p - __ldg(&g_csum[r]);
                }
            }
        }
    }

    // ---- GEMM2 (dup-h): dz[128x64] = h[128x256] @ W2s[256x64], chunked via smem ----
    // hsu[row][col] = {h,h} (u64, stride 66); W2s read as contiguous u64 pairs.
    int rg = tid>>4, dg = tid&15;       // rows rg*4..+3 ; d cols dg*4..+3
    unsigned long long dz2[4][2];
    {
        const unsigned long long* bp = (const unsigned long long*)&b2s[dg*4];
        unsigned long long bb0 = bp[0], bb1 = bp[1];
        #pragma unroll
        for (int i=0;i<4;i++){ dz2[i][0] = bb0; dz2[i][1] = bb1; }
    }

    for (int ci=0; ci<4; ci++){
        __syncthreads();    // GEMM1/zs reads done (ci=0); prior chunk reads done (ci>0)
        if ((hx>>3) == ci){
            int hb = (hx&7)*8;
            #pragma unroll
            for (int i=0;i<8;i++)
                #pragma unroll
                for (int j=0;j<4;j++){
                    uint32_t u0, u1;
                    UNPACK2(u0, u1, acc2[i][j]);
                    unsigned long long d0p, d1p;
                    PACK2(d0p, u0, u0);
                    PACK2(d1p, u1, u1);
                    hsu[(ry*8+i)*66 + hb + 2*j]     = d0p;
                    hsu[(ry*8+i)*66 + hb + 2*j + 1] = d1p;
                }
        }
        __syncthreads();
        #pragma unroll 4
        for (int hk=0; hk<64; hk++){
            const ulonglong2* wp = (const ulonglong2*)&W2s[(ci*64+hk)*DD + dg*4];
            ulonglong2 ww = wp[0];
            #pragma unroll
            for (int i=0;i<4;i++){
                unsigned long long h2 = hsu[(rg*4+i)*66 + hk];
                FFMA2(dz2[i][0], h2, ww.x);
                FFMA2(dz2[i][1], h2, ww.y);
            }
        }
    }
    #pragma unroll
    for (int i=0;i<4;i++){
        uint32_t a0,a1,a2v,a3;
        UNPACK2(a0, a1, dz2[i][0]);
        UNPACK2(a2v, a3, dz2[i][1]);
        float4 o = make_float4(__uint_as_float(a0), __uint_as_float(a1),
                               __uint_as_float(a2v), __uint_as_float(a3));
        *(float4*)&g_kz[stage][(size_t)(row0+rg*4+i)*DD + dg*4] = o;
    }
}

// ---------------- combine: y += dt*sum b_j k_j ; logp += dt*sum b_j kd_j ----------------
__global__ void combine_kernel(float dt){
    int i = blockIdx.x*256 + threadIdx.x;   // over BB*DD/4 float4
    const float b0 = (float)(35.0/384.0);
    const float b2 = (float)(500.0/1113.0);
    const float b3 = (float)(125.0/192.0);
    const float b4 = (float)(-2187.0/6784.0);
    const float b5 = (float)(11.0/84.0);
    float4 y = ((float4*)g_y)[i];
    float4 k0 = ((const float4*)g_kz[0])[i];
    float4 k2 = ((const float4*)g_kz[2])[i];
    float4 k3 = ((const float4*)g_kz[3])[i];
    float4 k4 = ((const float4*)g_kz[4])[i];
    float4 k5 = ((const float4*)g_kz[5])[i];
    float sx = b0*k0.x + b2*k2.x + b3*k3.x + b4*k4.x + b5*k5.x;
    float sy = b0*k0.y + b2*k2.y + b3*k3.y + b4*k4.y + b5*k5.y;
    float sz = b0*k0.z + b2*k2.z + b3*k3.z + b4*k4.z + b5*k5.z;
    float sw = b0*k0.w + b2*k2.w + b3*k3.w + b4*k4.w + b5*k5.w;
    y.x = fmaf(dt, sx, y.x); y.y = fmaf(dt, sy, y.y);
    y.z = fmaf(dt, sz, y.z); y.w = fmaf(dt, sw, y.w);
    ((float4*)g_y)[i] = y;
    if (i < BB){
        float s = b0*g_kd[0][i] + b2*g_kd[2][i] + b3*g_kd[3][i] + b4*g_kd[4][i] + b5*g_kd[5][i];
        g_logp[i] = fmaf(dt, s, g_logp[i]);
    }
}

// ---------------- epilogue: out = [z flat | log_px] ----------------
__global__ void final_kernel(float* __restrict__ out, int out_size){
    int gw = blockIdx.x*256 + threadIdx.x;
    int r = gw >> 5, lane = gw & 31;       // one warp per row
    float z0 = g_y[r*DD + lane];
    float z1 = g_y[r*DD + 32 + lane];
    out[r*DD + lane]      = z0;
    out[r*DD + 32 + lane] = z1;
    float s = fmaf(z0, z0, z1*z1);
    #pragma unroll
    for (int o=16;o;o>>=1) s += __shfl_xor_sync(0xffffffffu, s, o);
    if (lane==0){
        int oidx = BB*DD + r;
        if (oidx < out_size)
            out[oidx] = fmaf(-0.5f, s, -((float)DD)*0.91893853320467274178f) - g_logp[r];
    }
}

// ---------------- host ----------------
static const double A1t[1]={0.2};
static const double A2t[2]={3.0/40.0, 9.0/40.0};
static const double A3t[3]={44.0/45.0, -56.0/15.0, 32.0/9.0};
static const double A4t[4]={19372.0/6561.0, -25360.0/2187.0, 64448.0/6561.0, -212.0/729.0};
static const double A5t[5]={9017.0/3168.0, -355.0/33.0, 46732.0/5247.0, 49.0/176.0, -5103.0/18656.0};
static const double* ATAB[6]={0, A1t, A2t, A3t, A4t, A5t};
static const double CTAB[6]={0.0, 0.2, 0.3, 0.8, 8.0/9.0, 1.0};

extern "C" void kernel_launch(void* const* d_in, const int* in_sizes, int n_in,
                              void* d_out, int out_size){
    const float* y  = (const float*)d_in[0];
    const float* e  = (const float*)d_in[1];
    const float* W1 = (const float*)d_in[2];
    const float* b1 = (const float*)d_in[3];
    const float* W2 = (const float*)d_in[4];
    const float* b2 = (const float*)d_in[5];

    cudaFuncSetAttribute(rhs_kernel,        cudaFuncAttributeMaxDynamicSharedMemorySize, SMEM_RHS_BYTES);
    cudaFuncSetAttribute(precompute_kernel, cudaFuncAttributeMaxDynamicSharedMemorySize, 147456);

    init_kernel<<<8192,256>>>(y);
    precompute_kernel<<<512,512,147456>>>(e, W1, W2);

    double dt = 1.0/8.0;
    for (int s=0; s<8; s++){
        double t0 = s*dt;
        for (int i=0; i<6; i++){
            float cf[5] = {0.f,0.f,0.f,0.f,0.f};
            for (int j=0; j<i; j++) cf[j] = (float)(dt*ATAB[i][j]);
            rhs_kernel<<<256,512,SMEM_RHS_BYTES>>>(
                (float)(t0 + CTAB[i]*dt), i, cf[0],cf[1],cf[2],cf[3],cf[4],
                W1, b1, W2, b2);
        }
        combine_kernel<<<2048,256>>>((float)dt);
    }
    final_kernel<<<4096,256>>>((float*)d_out, out_size);
}

// round 17
// speedup vs baseline: 1.6940x; 1.0847x over previous
#include <cuda_runtime.h>
#include <stdint.h>
#include <math.h>

#define BB 32768
#define DD 64
#define HH 256

// ---------------- device scratch (static, no runtime allocation) ----------------
__device__ float g_y[BB*DD];
__device__ float g_logp[BB];
__device__ float g_kz[6][BB*DD];
__device__ float g_kd[6][BB];
__device__ float g_c[BB*HH];
__device__ float g_csum[BB];
__device__ unsigned long long g_w2kp[128*64];   // {W2[2k][d], W2[2k+1][d]} packed pairs

// ---------------- packed f32x2 helpers (FFMA2: only reachable via explicit PTX) ----------------
#define FFMA2(acc, a, b) \
    asm("fma.rn.f32x2 %0, %1, %2, %3;" : "=l"(acc) : "l"(a), "l"(b), "l"(acc))
#define PACK2(dst, lo, hi) \
    asm("mov.b64 %0, {%1, %2};" : "=l"(dst) : "r"(lo), "r"(hi))
#define UNPACK2(lo, hi, src) \
    asm("mov.b64 {%0, %1}, %2;" : "=r"(lo), "=r"(hi) : "l"(src))

// 32-byte evict_last global load (v8.b32 is the only f32-class form ptxas accepts)
__device__ __forceinline__ void ldg_evl8(const float* p, float4& lo, float4& hi){
    asm("ld.global.nc.L2::evict_last.v8.b32 {%0,%1,%2,%3,%4,%5,%6,%7}, [%8];"
        : "=f"(lo.x), "=f"(lo.y), "=f"(lo.z), "=f"(lo.w),
          "=f"(hi.x), "=f"(hi.y), "=f"(hi.z), "=f"(hi.w)
        : "l"(p));
}

// accurate fast tanh: 2 MUFU (ex2, rcp); ~1e-6 rel err
__device__ __forceinline__ float tanh_fast(float x){
    float a = fabsf(x);
    float m = a * -2.8853900817779268f;   // -2*log2(e)
    float e; asm("ex2.approx.f32 %0, %1;" : "=f"(e) : "f"(m));
    float den = 1.f + e;
    float r; asm("rcp.approx.f32 %0, %1;" : "=f"(r) : "f"(den));
    return copysignf((1.f - e) * r, x);
}

// ---------------- init: copy y, zero logp ----------------
__global__ void init_kernel(const float* __restrict__ y){
    int i = blockIdx.x*256 + threadIdx.x;      // grid covers BB*DD exactly
    g_y[i] = y[i];
    if (i < BB) g_logp[i] = 0.f;
}

// ---------------- prep: pack W2 k-pairs ----------------
__global__ void prep_kernel(const float* __restrict__ W2){
    int i = blockIdx.x*256 + threadIdx.x;   // 8192
    int k2 = i >> 6, d = i & 63;
    uint32_t lo = __float_as_uint(W2[(size_t)(2*k2)*DD + d]);
    uint32_t hi = __float_as_uint(W2[(size_t)(2*k2+1)*DD + d]);
    unsigned long long p; PACK2(p, lo, hi);
    g_w2kp[i] = p;
}

// ---------------- precompute: c = (e@W2^T) * (e@W1z), csum = row-sum(c) ----------------
__global__ __launch_bounds__(512,1) void precompute_kernel(
    const float* __restrict__ e, const float* __restrict__ W1, const float* __restrict__ W2){
    extern __shared__ float sm[];
    float* W1s = sm;            // [64][256]
    float* W2T = sm + 16384;    // [64][256]  (transposed W2)
    float* es  = sm + 32768;    // [64][64]
    int tid = threadIdx.x;
    int row0 = blockIdx.x*64;

    for (int i=tid; i<4096; i+=512) ((float4*)W1s)[i] = ((const float4*)W1)[i];
    for (int i=tid; i<HH*DD; i+=512){ int h = i>>6, d = i&63; W2T[d*HH + h] = W2[i]; }
    for (int i=tid; i<1024; i+=512) ((float4*)es)[i] = ((const float4*)(e + (size_t)row0*DD))[i];
    __syncthreads();

    int ry = tid>>5, hx = tid&31;   // rows ry*4..+3, h cols hx*8..+7
    float s1[4][8], s2[4][8];
    #pragma unroll
    for (int i=0;i<4;i++)
        #pragma unroll
        for (int j=0;j<8;j++){ s1[i][j]=0.f; s2[i][j]=0.f; }

    for (int d=0; d<DD; d++){
        float ev[4];
        #pragma unroll
        for (int i=0;i<4;i++) ev[i] = es[(ry*4+i)*DD + d];
        const float* p1 = &W1s[d*HH + hx*8];
        const float* p2 = &W2T[d*HH + hx*8];
        float4 a1 = *(const float4*)p1,  b1v = *(const float4*)(p1+4);
        float4 a2 = *(const float4*)p2,  b2v = *(const float4*)(p2+4);
        float w1v[8] = {a1.x,a1.y,a1.z,a1.w,b1v.x,b1v.y,b1v.z,b1v.w};
        float w2v[8] = {a2.x,a2.y,a2.z,a2.w,b2v.x,b2v.y,b2v.z,b2v.w};
        #pragma unroll
        for (int i=0;i<4;i++)
            #pragma unroll
            for (int j=0;j<8;j++){
                s2[i][j] = fmaf(ev[i], w1v[j], s2[i][j]);
                s1[i][j] = fmaf(ev[i], w2v[j], s1[i][j]);
            }
    }
    #pragma unroll
    for (int i=0;i<4;i++){
        float cv[8]; float p = 0.f;
        #pragma unroll
        for (int j=0;j<8;j++){ cv[j] = s1[i][j]*s2[i][j]; p += cv[j]; }
        int r = row0 + ry*4 + i;
        float4* dst = (float4*)&g_c[(size_t)r*HH + hx*8];
        dst[0] = make_float4(cv[0],cv[1],cv[2],cv[3]);
        dst[1] = make_float4(cv[4],cv[5],cv[6],cv[7]);
        #pragma unroll
        for (int o=16;o;o>>=1) p += __shfl_xor_sync(0xffffffffu, p, o);
        if (hx==0) g_csum[r] = p;
    }
}

// ---------------- fused RHS (packed f32x2; z-dup GEMM1, k-pair GEMM2) ----------------
// SMEM float-index map:
//   W1s f32 [64][256]      : 0     .. 16384  (64KB)
//   w2s u64 [128][64]      : 16384 .. 32768  (64KB, k-pair image)
//   union {                : 32768 .. 49152  (64KB)
//     zdup u64 [128][64]     (phase A: {z,z} per element)
//     hsu  u64 [128][33]     (phase B: h k-pairs, chunk-local 32 + pad)
//   }
//   tb  [256]              : 49152 .. 49408
//   b2s [64]               : 49408 .. 49472
#define SMEM_RHS_BYTES (49472*4)

__global__ __launch_bounds__(512,1) void rhs_kernel(
    float t, int stage, float c0,float c1,float c2,float c3,float c4,
    const float* __restrict__ W1, const float* __restrict__ b1,
    const float* __restrict__ b2){
    extern __shared__ float sm[];
    float* W1s = sm;
    unsigned long long* w2s  = (unsigned long long*)(sm + 16384);
    unsigned long long* zdup = (unsigned long long*)(sm + 32768);
    unsigned long long* hsu  = (unsigned long long*)(sm + 32768);
    float* tb   = sm + 49152;
    float* b2s  = sm + 49408;
    int tid = threadIdx.x;
    int row0 = blockIdx.x*128;

    for (int i=tid; i<4096; i+=512) ((float4*)W1s)[i] = __ldg(((const float4*)W1) + i);
    for (int i=tid; i<4096; i+=512) ((float4*)w2s)[i] = __ldg(((const float4*)g_w2kp) + i);
    if (tid < HH)                 tb[tid]       = fmaf(t, __ldg(&W1[DD*HH + tid]), __ldg(&b1[tid]));
    if (tid >= HH && tid < HH+DD) b2s[tid-HH]   = __ldg(&b2[tid-HH]);

    const float cf[5] = {c0,c1,c2,c3,c4};
    {
        const float4* ybase = (const float4*)(g_y + (size_t)row0*DD);
        for (int i=tid; i<2048; i+=512){
            float4 v = ybase[i];
            for (int j=0;j<stage;j++){
                float4 k = ((const float4*)(g_kz[j] + (size_t)row0*DD))[i];
                v.x = fmaf(cf[j],k.x,v.x); v.y = fmaf(cf[j],k.y,v.y);
                v.z = fmaf(cf[j],k.z,v.z); v.w = fmaf(cf[j],k.w,v.w);
            }
            int row = i >> 4, d4 = (i & 15) * 4;
            unsigned long long p0,p1,p2,p3;
            PACK2(p0, __float_as_uint(v.x), __float_as_uint(v.x));
            PACK2(p1, __float_as_uint(v.y), __float_as_uint(v.y));
            PACK2(p2, __float_as_uint(v.z), __float_as_uint(v.z));
            PACK2(p3, __float_as_uint(v.w), __float_as_uint(v.w));
            ulonglong2* dst = (ulonglong2*)&zdup[row*64 + d4];
            dst[0] = make_ulonglong2(p0, p1);
            dst[1] = make_ulonglong2(p2, p3);
        }
    }
    __syncthreads();

    // ---- GEMM1 (packed, z-dup): a[128x256] = z[128x64] @ W1s[64x256]
    // thread (ry,hx): rows ry*8..+7 ; h cols hx*8..+7 (4 packed h-pairs)
    int ry = tid>>5, hx = tid&31;
    unsigned long long acc2[8][4];
    #pragma unroll
    for (int i=0;i<8;i++)
        #pragma unroll
        for (int j=0;j<4;j++) acc2[i][j] = 0ull;

    for (int d0=0; d0<DD; d0+=4){
        #pragma unroll
        for (int hf=0; hf<2; hf++){
            int db = d0 + hf*2;
            unsigned long long wv0[4], wv1[4];
            {
                const ulonglong2* wp0 = (const ulonglong2*)&W1s[(db+0)*HH + hx*8];
                const ulonglong2* wp1 = (const ulonglong2*)&W1s[(db+1)*HH + hx*8];
                ulonglong2 a0 = wp0[0], b0v = wp0[1];
                ulonglong2 a1 = wp1[0], b1v = wp1[1];
                wv0[0]=a0.x; wv0[1]=a0.y; wv0[2]=b0v.x; wv0[3]=b0v.y;
                wv1[0]=a1.x; wv1[1]=a1.y; wv1[2]=b1v.x; wv1[3]=b1v.y;
            }
            #pragma unroll
            for (int i=0;i<8;i++){
                ulonglong2 zz = *(const ulonglong2*)&zdup[(ry*8+i)*64 + db];
                #pragma unroll
                for (int j=0;j<4;j++) FFMA2(acc2[i][j], zz.x, wv0[j]);
                #pragma unroll
                for (int j=0;j<4;j++) FFMA2(acc2[i][j], zz.y, wv1[j]);
            }
        }
    }

    // ---- bias + tanh + divergence dot (skipped at stage 1: B_TAB[1]==0) ----
    size_t grow0 = (size_t)row0;
    const bool do_div = (stage != 1);
    {
        float4 tbA = *(const float4*)&tb[hx*8];
        float4 tbB = *(const float4*)&tb[hx*8 + 4];
        float tba[8] = {tbA.x,tbA.y,tbA.z,tbA.w,tbB.x,tbB.y,tbB.z,tbB.w};
        size_t crow = (grow0 + ry*8)*HH + hx*8;
        float4 cA, cB;
        if (do_div) ldg_evl8(g_c + crow, cA, cB);
        #pragma unroll
        for (int i=0;i<8;i++){
            float4 c0v = cA, c1v = cB;
            if (do_div && i<7) ldg_evl8(g_c + crow + (size_t)(i+1)*HH, cA, cB);
            float hv[8];
            #pragma unroll
            for (int j=0;j<4;j++){
                uint32_t u0, u1;
                UNPACK2(u0, u1, acc2[i][j]);
                hv[2*j]   = tanh_fast(__uint_as_float(u0) + tba[2*j]);
                hv[2*j+1] = tanh_fast(__uint_as_float(u1) + tba[2*j+1]);
                PACK2(acc2[i][j], __float_as_uint(hv[2*j]), __float_as_uint(hv[2*j+1]));
            }
            if (do_div){
                float p;
                p  = c0v.x*hv[0]*hv[0];
                p  = fmaf(c0v.y*hv[1], hv[1], p);
                p  = fmaf(c0v.z*hv[2], hv[2], p);
                p  = fmaf(c0v.w*hv[3], hv[3], p);
                p  = fmaf(c1v.x*hv[4], hv[4], p);
                p  = fmaf(c1v.y*hv[5], hv[5], p);
                p  = fmaf(c1v.z*hv[6], hv[6], p);
                p  = fmaf(c1v.w*hv[7], hv[7], p);
                #pragma unroll
                for (int o=16;o;o>>=1) p += __shfl_xor_sync(0xffffffffu, p, o);
                if (hx==0){
                    int r = row0 + ry*8 + i;
                    g_kd[stage][r] = p - __ldg(&g_csum[r]);
                }
            }
        }
    }

    // ---- GEMM2 (k-pair): dz[128x64] = h[128x256] @ W2[256x64]
    // acc lanes = (even-k partial, odd-k partial); h pairs from acc2 via LDS.64;
    // W2 pairs from w2s image. thread (rg,dg): rows rg*4..+3, d cols {2dg,2dg+1,2dg+32,2dg+33}.
    int rg = tid>>4, dg = tid&15;
    unsigned long long dzk[4][4];
    #pragma unroll
    for (int i=0;i<4;i++)
        #pragma unroll
        for (int c=0;c<4;c++) dzk[i][c] = 0ull;

    for (int ci=0; ci<4; ci++){
        __syncthreads();    // zdup reads / prior chunk reads complete
        if ((hx>>3) == ci){
            int pb = (hx&7)*4;
            #pragma unroll
            for (int i=0;i<8;i++)
                #pragma unroll
                for (int j=0;j<4;j++)
                    hsu[(ry*8+i)*33 + pb + j] = acc2[i][j];
        }
        __syncthreads();
        #pragma unroll 4
        for (int k2=0; k2<32; k2++){
            ulonglong2 wA = *(const ulonglong2*)&w2s[(ci*32+k2)*64 + 2*dg];
            ulonglong2 wB = *(const ulonglong2*)&w2s[(ci*32+k2)*64 + 2*dg + 32];
            #pragma unroll
            for (int i=0;i<4;i++){
                unsigned long long h2 = hsu[(rg*4+i)*33 + k2];
                FFMA2(dzk[i][0], h2, wA.x);
                FFMA2(dzk[i][1], h2, wA.y);
                FFMA2(dzk[i][2], h2, wB.x);
                FFMA2(dzk[i][3], h2, wB.y);
            }
        }
    }

    // final: sum even/odd lanes, add bias, store
    float bb0 = b2s[2*dg],      bb1 = b2s[2*dg+1];
    float bb2 = b2s[2*dg+32],   bb3 = b2s[2*dg+33];
    #pragma unroll
    for (int i=0;i<4;i++){
        float s[4];
        #pragma unroll
        for (int c=0;c<4;c++){
            uint32_t lo, hi;
            UNPACK2(lo, hi, dzk[i][c]);
            s[c] = __uint_as_float(lo) + __uint_as_float(hi);
        }
        size_t base = (size_t)(row0 + rg*4 + i)*DD;
        *(float2*)&g_kz[stage][base + 2*dg]      = make_float2(s[0]+bb0, s[1]+bb1);
        *(float2*)&g_kz[stage][base + 2*dg + 32] = make_float2(s[2]+bb2, s[3]+bb3);
    }
}

// ---------------- combine: y += dt*sum b_j k_j ; logp += dt*sum b_j kd_j ----------------
__global__ void combine_kernel(float dt){
    int i = blockIdx.x*256 + threadIdx.x;   // over BB*DD/4 float4
    const float b0 = (float)(35.0/384.0);
    const float b2 = (float)(500.0/1113.0);
    const float b3 = (float)(125.0/192.0);
    const float b4 = (float)(-2187.0/6784.0);
    const float b5 = (float)(11.0/84.0);
    float4 y = ((float4*)g_y)[i];
    float4 k0 = ((const float4*)g_kz[0])[i];
    float4 k2 = ((const float4*)g_kz[2])[i];
    float4 k3 = ((const float4*)g_kz[3])[i];
    float4 k4 = ((const float4*)g_kz[4])[i];
    float4 k5 = ((const float4*)g_kz[5])[i];
    float sx = b0*k0.x + b2*k2.x + b3*k3.x + b4*k4.x + b5*k5.x;
    float sy = b0*k0.y + b2*k2.y + b3*k3.y + b4*k4.y + b5*k5.y;
    float sz = b0*k0.z + b2*k2.z + b3*k3.z + b4*k4.z + b5*k5.z;
    float sw = b0*k0.w + b2*k2.w + b3*k3.w + b4*k4.w + b5*k5.w;
    y.x = fmaf(dt, sx, y.x); y.y = fmaf(dt, sy, y.y);
    y.z = fmaf(dt, sz, y.z); y.w = fmaf(dt, sw, y.w);
    ((float4*)g_y)[i] = y;
    if (i < BB){
        float s = b0*g_kd[0][i] + b2*g_kd[2][i] + b3*g_kd[3][i] + b4*g_kd[4][i] + b5*g_kd[5][i];
        g_logp[i] = fmaf(dt, s, g_logp[i]);
    }
}

// ---------------- epilogue: out = [z flat | log_px] ----------------
__global__ void final_kernel(float* __restrict__ out, int out_size){
    int gw = blockIdx.x*256 + threadIdx.x;
    int r = gw >> 5, lane = gw & 31;       // one warp per row
    float z0 = g_y[r*DD + lane];
    float z1 = g_y[r*DD + 32 + lane];
    out[r*DD + lane]      = z0;
    out[r*DD + 32 + lane] = z1;
    float s = fmaf(z0, z0, z1*z1);
    #pragma unroll
    for (int o=16;o;o>>=1) s += __shfl_xor_sync(0xffffffffu, s, o);
    if (lane==0){
        int oidx = BB*DD + r;
        if (oidx < out_size)
            out[oidx] = fmaf(-0.5f, s, -((float)DD)*0.91893853320467274178f) - g_logp[r];
    }
}

// ---------------- host ----------------
static const double A1t[1]={0.2};
static const double A2t[2]={3.0/40.0, 9.0/40.0};
static const double A3t[3]={44.0/45.0, -56.0/15.0, 32.0/9.0};
static const double A4t[4]={19372.0/6561.0, -25360.0/2187.0, 64448.0/6561.0, -212.0/729.0};
static const double A5t[5]={9017.0/3168.0, -355.0/33.0, 46732.0/5247.0, 49.0/176.0, -5103.0/18656.0};
static const double* ATAB[6]={0, A1t, A2t, A3t, A4t, A5t};
static const double CTAB[6]={0.0, 0.2, 0.3, 0.8, 8.0/9.0, 1.0};

extern "C" void kernel_launch(void* const* d_in, const int* in_sizes, int n_in,
                              void* d_out, int out_size){
    const float* y  = (const float*)d_in[0];
    const float* e  = (const float*)d_in[1];
    const float* W1 = (const float*)d_in[2];
    const float* b1 = (const float*)d_in[3];
    const float* W2 = (const float*)d_in[4];
    const float* b2 = (const float*)d_in[5];

    cudaFuncSetAttribute(rhs_kernel,        cudaFuncAttributeMaxDynamicSharedMemorySize, SMEM_RHS_BYTES);
    cudaFuncSetAttribute(precompute_kernel, cudaFuncAttributeMaxDynamicSharedMemorySize, 147456);

    init_kernel<<<8192,256>>>(y);
    prep_kernel<<<32,256>>>(W2);
    precompute_kernel<<<512,512,147456>>>(e, W1, W2);

    double dt = 1.0/8.0;
    for (int s=0; s<8; s++){
        double t0 = s*dt;
        for (int i=0; i<6; i++){
            float cf[5] = {0.f,0.f,0.f,0.f,0.f};
            for (int j=0; j<i; j++) cf[j] = (float)(dt*ATAB[i][j]);
            rhs_kernel<<<256,512,SMEM_RHS_BYTES>>>(
                (float)(t0 + CTAB[i]*dt), i, cf[0],cf[1],cf[2],cf[3],cf[4],
                W1, b1, b2);
        }
        combine_kernel<<<2048,256>>>((float)dt);
    }
    final_kernel<<<4096,256>>>((float*)d_out, out_size);
}